// round 9
// baseline (speedup 1.0000x reference)
#include <cuda_runtime.h>
#include <math.h>
#include <stdint.h>

#define BS 16
#define TT 20
#define NN 512
#define EE 64
#define LL 8
#define STEPS 12
#define NROWS 19   // rows of skill_seq used as S-row indices (0..18)

// ---------------- scratch (device globals; no allocation allowed) ----------
__device__ float g_S[BS * 2 * NROWS * NN];   // S[b][k][r][n] = adj[k,b,sh_r,n] + adj2[k,b,sh_r,n]
__device__ float g_hA[BS * NN * EE];
__device__ float g_hB[BS * NN * EE];
__device__ float g_ew[STEPS * BS * LL];      // exp(-dtw)

// ---------------- helpers --------------------------------------------------
// HW tanh: single MUFU op (sm_75+), abs err ~6e-4
__device__ __forceinline__ float tanha(float x) {
    float r;
    asm("tanh.approx.f32 %0, %1;" : "=f"(r) : "f"(x));
    return r;
}

__device__ __forceinline__ float warp_sum(float v) {
#pragma unroll
    for (int o = 16; o > 0; o >>= 1) v += __shfl_xor_sync(0xffffffffu, v, o);
    return v;
}

// packed f32x2 FMA: d = a*b + d
__device__ __forceinline__ void fma2(unsigned long long& d,
                                     unsigned long long a,
                                     unsigned long long b) {
    asm("fma.rn.f32x2 %0, %1, %2, %0;" : "+l"(d) : "l"(a), "l"(b));
}
__device__ __forceinline__ float red2(unsigned long long p) {
    float2 r;
    asm("mov.b64 {%0,%1}, %2;" : "=f"(r.x), "=f"(r.y) : "l"(p));
    return r.x + r.y;
}

// ---------------- hidden0 --------------------------------------------------
__global__ void k_init_hidden(const int* __restrict__ skill,
                              const int* __restrict__ label,
                              const float* __restrict__ emb,
                              float* __restrict__ hid) {
    int b = blockIdx.x;
    int n = blockIdx.y * 4 + (threadIdx.x >> 6);
    int e = threadIdx.x & 63;
    float v = 0.0f;
#pragma unroll
    for (int l = LL - 1; l >= 0; --l) {
        if (skill[b * TT + l] == n) {
            float lp = (label[b * TT + l] == 0) ? -1.0f : 1.0f;
            v = emb[n * EE + e] * lp;
            break;
        }
    }
    hid[(b * NN + n) * EE + e] = v;
}

// ---------------- exp(-dtw) ------------------------------------------------
__global__ void k_ew(const int* __restrict__ timeq) {
    int idx = blockIdx.x * blockDim.x + threadIdx.x;
    if (idx >= STEPS * BS * LL) return;
    int l = idx % LL;
    int b = (idx / LL) % BS;
    int t = idx / (LL * BS);
    float d = fabsf((float)timeq[b * TT + t + l] - (float)timeq[b * TT + t + LL]) + 1e-6f;
    float dtw = logf(d) / logf(5.0f);
    g_ew[idx] = expf(-dtw);
}

// ---------------- S rows: adj + adj@adj/N, only the 19 needed rows ---------
__global__ void k_S(const int* __restrict__ skill, const float* __restrict__ adj) {
    int chunk = blockIdx.x, k = blockIdx.y, b = blockIdx.z;
    int n = chunk * 128 + threadIdx.x;

    __shared__ float arows[NROWS][NN];
    __shared__ int rowskill[NROWS];
    if (threadIdx.x < NROWS) rowskill[threadIdx.x] = skill[b * TT + threadIdx.x];
    __syncthreads();

    const float* A = adj + ((size_t)k * BS + b) * NN * NN;
    for (int idx = threadIdx.x; idx < NROWS * NN; idx += 128) {
        int r = idx >> 9;
        int j = idx & 511;
        arows[r][j] = A[rowskill[r] * NN + j];
    }
    __syncthreads();

    float acc[NROWS];
#pragma unroll
    for (int r = 0; r < NROWS; r++) acc[r] = 0.0f;

#pragma unroll 4
    for (int j = 0; j < NN; j++) {
        float c = A[j * NN + n];
#pragma unroll
        for (int r = 0; r < NROWS; r++) acc[r] += arows[r][j] * c;
    }

    const float inv = 1.0f / (float)NN;
#pragma unroll
    for (int r = 0; r < NROWS; r++) {
        g_S[(((size_t)b * 2 + k) * NROWS + r) * NN + n] = arows[r][n] + acc[r] * inv;
    }
}

// ---------------- f-network at target node (one warp) ----------------------
__device__ __forceinline__ void fnet_warp(
    float x0, float x1, int lane, float* sx,
    const float* __restrict__ fw1, const float* __restrict__ fb1,
    const float* __restrict__ ln1g, const float* __restrict__ ln1b,
    const float* __restrict__ fw2, const float* __restrict__ fb2,
    const float* __restrict__ ln2g, const float* __restrict__ ln2b,
    const float* __restrict__ fw3, const float* __restrict__ fb3,
    float* __restrict__ outp) {

    __syncwarp();
    sx[lane] = x0; sx[lane + 32] = x1;
    __syncwarp();
    float t0 = fb1[lane], t1 = fb1[lane + 32];
#pragma unroll 8
    for (int f = 0; f < 64; f++) {
        float v = sx[f];
        t0 += v * fw1[lane * 64 + f];
        t1 += v * fw1[(lane + 32) * 64 + f];
    }
    float h0 = x0 + (t0 > 0.0f ? t0 : 0.01f * t0);
    float h1 = x1 + (t1 > 0.0f ? t1 : 0.01f * t1);

    float m = warp_sum(h0 + h1) * (1.0f / 64.0f);
    float d0 = h0 - m, d1 = h1 - m;
    float var = warp_sum(d0 * d0 + d1 * d1) * (1.0f / 64.0f);
    float r = rsqrtf(var + 1e-5f);
    float y0 = d0 * r * ln1g[lane] + ln1b[lane];
    float y1 = d1 * r * ln1g[lane + 32] + ln1b[lane + 32];

    __syncwarp();
    sx[lane] = y0; sx[lane + 32] = y1;
    __syncwarp();
    t0 = fb2[lane]; t1 = fb2[lane + 32];
#pragma unroll 8
    for (int f = 0; f < 64; f++) {
        float v = sx[f];
        t0 += v * fw2[lane * 64 + f];
        t1 += v * fw2[(lane + 32) * 64 + f];
    }
    h0 += (t0 > 0.0f ? t0 : 0.01f * t0);
    h1 += (t1 > 0.0f ? t1 : 0.01f * t1);

    m = warp_sum(h0 + h1) * (1.0f / 64.0f);
    d0 = h0 - m; d1 = h1 - m;
    var = warp_sum(d0 * d0 + d1 * d1) * (1.0f / 64.0f);
    r = rsqrtf(var + 1e-5f);
    float z0 = d0 * r * ln2g[lane] + ln2b[lane];
    float z1 = d1 * r * ln2g[lane + 32] + ln2b[lane + 32];

    float l0 = warp_sum(z0 * fw3[lane] + z1 * fw3[lane + 32]);
    float l1 = warp_sum(z0 * fw3[64 + lane] + z1 * fw3[64 + lane + 32]);
    if (lane == 0) {
        l0 += fb3[0]; l1 += fb3[1];
        *outp = 1.0f / (1.0f + expf(l0 - l1));
    }
    __syncwarp();
}

// ---------------- fused step kernel ----------------------------------------
// grid (32, BS), block 256 = 8 warps, each warp 2 nodes.
// smem (floats): sW1b 4352 | sW2 4352 | sM1 4096 | sA 512 | sHX 512 |
//                sB2 64 | sEW 8 | sSH 8        = 13904 fl = 55616 B -> 4/SM
#define SW_STRIDE 68
#define SMEM_FLOATS 13904
#define SMEM_BYTES  (SMEM_FLOATS * 4)

__global__ __launch_bounds__(256, 4) void k_step(
    const float* __restrict__ hcur, float* __restrict__ hnext, int t,
    const int* __restrict__ skill,
    const float* __restrict__ fc1w, const float* __restrict__ fc1b,
    const float* __restrict__ fc2w, const float* __restrict__ fc2b,
    const float* __restrict__ fw1, const float* __restrict__ fb1,
    const float* __restrict__ ln1g, const float* __restrict__ ln1b,
    const float* __restrict__ fw2, const float* __restrict__ fb2,
    const float* __restrict__ ln2g, const float* __restrict__ ln2b,
    const float* __restrict__ fw3, const float* __restrict__ fb3,
    float* __restrict__ out) {

    extern __shared__ float s[];
    float* sW1b = s;                  // [e][f] stride 68
    float* sW2  = s + 4352;           // [e][f] stride 68
    float* sM1  = s + 8704;           // per-warp [8 l][64 f] stride 64
    float* sA   = s + 12800;          // [8 l][64 e]
    float* sHX  = s + 13312;          // per-warp 64-fl scratch (hh, hidden, fnet)
    float* sB2  = s + 13824;
    float* sEW  = s + 13888;
    int*   sSH  = (int*)(s + 13896);

    int b = blockIdx.y;
    int g = blockIdx.x;
    int tid = threadIdx.x;
    int w = tid >> 5;
    int lane = tid & 31;

    // --- stage W1b, W2 into smem (coalesced gmem, stride-68 rows) ---
    for (int idx = tid; idx < 64 * 64; idx += 256) {
        int e = idx >> 6, f = idx & 63;
        sW1b[e * SW_STRIDE + f] = fc1w[e * 128 + 64 + f];
        sW2[e * SW_STRIDE + f]  = fc2w[idx];
    }
    if (tid < 64) sB2[tid] = fc2b[tid];
    if (tid < 8) {
        sEW[tid] = g_ew[(t * BS + b) * LL + tid];
        sSH[tid] = skill[b * TT + t + tid];
    }
    __syncthreads();

    // --- phase 1: warp w computes A[w][:] = hh[w] @ W1a^T + b1 (W1a via L2) ---
    {
        int sl = sSH[w];
        sHX[w * 64 + lane]      = hcur[((b << 9) + sl) * EE + lane];
        sHX[w * 64 + lane + 32] = hcur[((b << 9) + sl) * EE + lane + 32];
        __syncwarp();
        const ulonglong2* wa0 = (const ulonglong2*)(fc1w + lane * 128);
        const ulonglong2* wa1 = (const ulonglong2*)(fc1w + (lane + 32) * 128);
        const unsigned long long* hv = (const unsigned long long*)(sHX + w * 64);
        unsigned long long a0 = 0ull, a1 = 0ull;
#pragma unroll
        for (int fp = 0; fp < 16; fp++) {
            ulonglong2 qa = __ldg(&wa0[fp]);
            ulonglong2 qb = __ldg(&wa1[fp]);
            unsigned long long m01 = hv[2 * fp], m23 = hv[2 * fp + 1];
            fma2(a0, m01, qa.x); fma2(a0, m23, qa.y);
            fma2(a1, m01, qb.x); fma2(a1, m23, qb.y);
        }
        sA[w * 64 + lane]      = red2(a0) + __ldg(&fc1b[lane]);
        sA[w * 64 + lane + 32] = red2(a1) + __ldg(&fc1b[lane + 32]);
    }
    __syncthreads();

    int tgt = __ldg(&skill[b * TT + t + LL]);
    float* myM1 = sM1 + w * 512;
    float* mysx = sHX + w * 64;
    const unsigned long long* hv = (const unsigned long long*)mysx;
    const ulonglong2* w1bA = (const ulonglong2*)(sW1b + lane * SW_STRIDE);
    const ulonglong2* w1bB = (const ulonglong2*)(sW1b + (lane + 32) * SW_STRIDE);
    const ulonglong2* w2A  = (const ulonglong2*)(sW2 + lane * SW_STRIDE);
    const ulonglong2* w2B  = (const ulonglong2*)(sW2 + (lane + 32) * SW_STRIDE);
    const ulonglong2* mv2  = (const ulonglong2*)myM1;

    int n0 = (((g << 3) + w) << 1);

#pragma unroll 1
    for (int i = 0; i < 2; i++) {
        int n = n0 + i;

        // hidden row of this node -> smem for packed broadcast
        mysx[lane]      = hcur[((b << 9) + n) * EE + lane];
        mysx[lane + 32] = hcur[((b << 9) + n) * EE + lane + 32];
        __syncwarp();

        // B = hidden[n] @ W1b^T  (f-pair packed)
        unsigned long long bp0 = 0ull, bp1 = 0ull;
#pragma unroll
        for (int fp = 0; fp < 16; fp++) {
            ulonglong2 qa = w1bA[fp];
            ulonglong2 qb = w1bB[fp];
            unsigned long long m01 = hv[2 * fp], m23 = hv[2 * fp + 1];
            fma2(bp0, m01, qa.x); fma2(bp0, m23, qa.y);
            fma2(bp1, m01, qb.x); fma2(bp1, m23, qb.y);
        }
        float B0 = red2(bp0), B1 = red2(bp1);

        // msg1 = tanh(A + B)   (single-MUFU tanh)
#pragma unroll
        for (int l = 0; l < 8; l++) {
            myM1[l * 64 + lane]      = tanha(sA[l * 64 + lane] + B0);
            myM1[l * 64 + lane + 32] = tanha(sA[l * 64 + lane + 32] + B1);
        }
        __syncwarp();

        // S rows prefetch (L2-resident uniform loads, overlap with fc2)
        float wr0[8], wr1[8];
#pragma unroll
        for (int l = 0; l < 8; l++) {
            wr0[l] = __ldg(&g_S[(((size_t)b * 2 + 0) * NROWS + (t + l)) * NN + n]);
            wr1[l] = __ldg(&g_S[(((size_t)b * 2 + 1) * NROWS + (t + l)) * NN + n]);
        }

        float b20 = sB2[lane], b21 = sB2[lane + 32];
        float ag00 = 0, ag01 = 0, ag10 = 0, ag11 = 0;

        // fc2 in two 4-l halves (keeps accumulators at 16 regs)
#pragma unroll
        for (int h = 0; h < 2; h++) {
            unsigned long long acc0[4], acc1[4];
#pragma unroll
            for (int l = 0; l < 4; l++) { acc0[l] = 0ull; acc1[l] = 0ull; }
#pragma unroll 4
            for (int fp = 0; fp < 16; fp++) {
                ulonglong2 qa = w2A[fp];
                ulonglong2 qb = w2B[fp];
#pragma unroll
                for (int l = 0; l < 4; l++) {
                    ulonglong2 m = mv2[(h * 4 + l) * 16 + fp];
                    fma2(acc0[l], m.x, qa.x); fma2(acc0[l], m.y, qa.y);
                    fma2(acc1[l], m.x, qb.x); fma2(acc1[l], m.y, qb.y);
                }
            }
#pragma unroll
            for (int l = 0; l < 4; l++) {
                int ll = h * 4 + l;
                float ewl = sEW[ll];
                float m0 = tanha(red2(acc0[l]) + b20) * ewl;
                float m1 = tanha(red2(acc1[l]) + b21) * ewl;
                ag00 += wr0[ll] * m0;  ag01 += wr0[ll] * m1;
                ag10 += wr1[ll] * m0;  ag11 += wr1[ll] * m1;
            }
        }

        // new_hidden = mean over k
        hnext[((b << 9) + n) * EE + lane]      = 0.5f * (ag00 + ag10);
        hnext[((b << 9) + n) * EE + lane + 32] = 0.5f * (ag01 + ag11);

        // prediction head only at the target node
        if (n == tgt) {
            fnet_warp(ag00, ag01, lane, mysx, fw1, fb1, ln1g, ln1b,
                      fw2, fb2, ln2g, ln2b, fw3, fb3,
                      &out[(t * BS + b) * 2 + 0]);
            fnet_warp(ag10, ag11, lane, mysx, fw1, fb1, ln1g, ln1b,
                      fw2, fb2, ln2g, ln2b, fw3, fb3,
                      &out[(t * BS + b) * 2 + 1]);
        }
        __syncwarp();
    }
}

// ---------------- launch ----------------------------------------------------
extern "C" void kernel_launch(void* const* d_in, const int* in_sizes, int n_in,
                              void* d_out, int out_size) {
    const int*   skill = (const int*)d_in[0];
    const int*   timeq = (const int*)d_in[1];
    const int*   label = (const int*)d_in[2];
    const float* adj   = (const float*)d_in[3];
    const float* emb   = (const float*)d_in[4];
    const float* fc1w  = (const float*)d_in[5];
    const float* fc1b  = (const float*)d_in[6];
    const float* fc2w  = (const float*)d_in[7];
    const float* fc2b  = (const float*)d_in[8];
    const float* fw1   = (const float*)d_in[9];
    const float* fb1   = (const float*)d_in[10];
    const float* ln1g  = (const float*)d_in[11];
    const float* ln1b  = (const float*)d_in[12];
    const float* fw2   = (const float*)d_in[13];
    const float* fb2   = (const float*)d_in[14];
    const float* ln2g  = (const float*)d_in[15];
    const float* ln2b  = (const float*)d_in[16];
    const float* fw3   = (const float*)d_in[17];
    const float* fb3   = (const float*)d_in[18];
    float* out = (float*)d_out;

    cudaFuncSetAttribute(k_step, cudaFuncAttributeMaxDynamicSharedMemorySize, SMEM_BYTES);

    float *hA, *hB;
    cudaGetSymbolAddress((void**)&hA, g_hA);
    cudaGetSymbolAddress((void**)&hB, g_hB);

    k_init_hidden<<<dim3(BS, NN / 4), 256>>>(skill, label, emb, hA);
    k_ew<<<3, 512>>>(timeq);
    k_S<<<dim3(4, 2, BS), 128>>>(skill, adj);

    for (int t = 0; t < STEPS; t++) {
        const float* hc = (t & 1) ? hB : hA;
        float*       hn = (t & 1) ? hA : hB;
        k_step<<<dim3(32, BS), 256, SMEM_BYTES>>>(
            hc, hn, t, skill,
            fc1w, fc1b, fc2w, fc2b,
            fw1, fb1, ln1g, ln1b, fw2, fb2, ln2g, ln2b, fw3, fb3,
            out);
    }
}

// round 10
// speedup vs baseline: 1.2369x; 1.2369x over previous
#include <cuda_runtime.h>
#include <math.h>
#include <stdint.h>

#define BS 16
#define TT 20
#define NN 512
#define EE 64
#define LL 8
#define STEPS 12
#define NROWS 19   // rows of skill_seq used as S-row indices (0..18)

// ---------------- scratch (device globals; no allocation allowed) ----------
__device__ float g_S[BS * 2 * NROWS * NN];   // S[b][k][r][n] = adj[k,b,sh_r,n] + adj2[k,b,sh_r,n]
__device__ float g_hA[BS * NN * EE];
__device__ float g_hB[BS * NN * EE];
__device__ float g_ew[STEPS * BS * LL];      // exp(-dtw)

// ---------------- helpers --------------------------------------------------
// HW tanh: single MUFU op, abs err ~6e-4 (measured rel_err 1.6e-6 end-to-end)
__device__ __forceinline__ float tanha(float x) {
    float r;
    asm("tanh.approx.f32 %0, %1;" : "=f"(r) : "f"(x));
    return r;
}

__device__ __forceinline__ float warp_sum(float v) {
#pragma unroll
    for (int o = 16; o > 0; o >>= 1) v += __shfl_xor_sync(0xffffffffu, v, o);
    return v;
}

// packed f32x2 FMA: d = a*b + d
__device__ __forceinline__ void fma2(unsigned long long& d,
                                     unsigned long long a,
                                     unsigned long long b) {
    asm("fma.rn.f32x2 %0, %1, %2, %0;" : "+l"(d) : "l"(a), "l"(b));
}
__device__ __forceinline__ float red2(unsigned long long p) {
    float2 r;
    asm("mov.b64 {%0,%1}, %2;" : "=f"(r.x), "=f"(r.y) : "l"(p));
    return r.x + r.y;
}

// ---------------- hidden0 --------------------------------------------------
__global__ void k_init_hidden(const int* __restrict__ skill,
                              const int* __restrict__ label,
                              const float* __restrict__ emb,
                              float* __restrict__ hid) {
    int b = blockIdx.x;
    int n = blockIdx.y * 4 + (threadIdx.x >> 6);
    int e = threadIdx.x & 63;
    float v = 0.0f;
#pragma unroll
    for (int l = LL - 1; l >= 0; --l) {
        if (skill[b * TT + l] == n) {
            float lp = (label[b * TT + l] == 0) ? -1.0f : 1.0f;
            v = emb[n * EE + e] * lp;
            break;
        }
    }
    hid[(b * NN + n) * EE + e] = v;
}

// ---------------- exp(-dtw) ------------------------------------------------
__global__ void k_ew(const int* __restrict__ timeq) {
    int idx = blockIdx.x * blockDim.x + threadIdx.x;
    if (idx >= STEPS * BS * LL) return;
    int l = idx % LL;
    int b = (idx / LL) % BS;
    int t = idx / (LL * BS);
    float d = fabsf((float)timeq[b * TT + t + l] - (float)timeq[b * TT + t + LL]) + 1e-6f;
    float dtw = logf(d) / logf(5.0f);
    g_ew[idx] = expf(-dtw);
}

// ---------------- S rows: adj + adj@adj/N, only the 19 needed rows ---------
__global__ void k_S(const int* __restrict__ skill, const float* __restrict__ adj) {
    int chunk = blockIdx.x, k = blockIdx.y, b = blockIdx.z;
    int n = chunk * 128 + threadIdx.x;

    __shared__ float arows[NROWS][NN];
    __shared__ int rowskill[NROWS];
    if (threadIdx.x < NROWS) rowskill[threadIdx.x] = skill[b * TT + threadIdx.x];
    __syncthreads();

    const float* A = adj + ((size_t)k * BS + b) * NN * NN;
    for (int idx = threadIdx.x; idx < NROWS * NN; idx += 128) {
        int r = idx >> 9;
        int j = idx & 511;
        arows[r][j] = A[rowskill[r] * NN + j];
    }
    __syncthreads();

    float acc[NROWS];
#pragma unroll
    for (int r = 0; r < NROWS; r++) acc[r] = 0.0f;

#pragma unroll 4
    for (int j = 0; j < NN; j++) {
        float c = A[j * NN + n];
#pragma unroll
        for (int r = 0; r < NROWS; r++) acc[r] += arows[r][j] * c;
    }

    const float inv = 1.0f / (float)NN;
#pragma unroll
    for (int r = 0; r < NROWS; r++) {
        g_S[(((size_t)b * 2 + k) * NROWS + r) * NN + n] = arows[r][n] + acc[r] * inv;
    }
}

// ---------------- f-network at target node (one warp) ----------------------
__device__ __forceinline__ void fnet_warp(
    float x0, float x1, int lane, float* sx,
    const float* __restrict__ fw1, const float* __restrict__ fb1,
    const float* __restrict__ ln1g, const float* __restrict__ ln1b,
    const float* __restrict__ fw2, const float* __restrict__ fb2,
    const float* __restrict__ ln2g, const float* __restrict__ ln2b,
    const float* __restrict__ fw3, const float* __restrict__ fb3,
    float* __restrict__ outp) {

    __syncwarp();
    sx[lane] = x0; sx[lane + 32] = x1;
    __syncwarp();
    float t0 = fb1[lane], t1 = fb1[lane + 32];
#pragma unroll 8
    for (int f = 0; f < 64; f++) {
        float v = sx[f];
        t0 += v * fw1[lane * 64 + f];
        t1 += v * fw1[(lane + 32) * 64 + f];
    }
    float h0 = x0 + (t0 > 0.0f ? t0 : 0.01f * t0);
    float h1 = x1 + (t1 > 0.0f ? t1 : 0.01f * t1);

    float m = warp_sum(h0 + h1) * (1.0f / 64.0f);
    float d0 = h0 - m, d1 = h1 - m;
    float var = warp_sum(d0 * d0 + d1 * d1) * (1.0f / 64.0f);
    float r = rsqrtf(var + 1e-5f);
    float y0 = d0 * r * ln1g[lane] + ln1b[lane];
    float y1 = d1 * r * ln1g[lane + 32] + ln1b[lane + 32];

    __syncwarp();
    sx[lane] = y0; sx[lane + 32] = y1;
    __syncwarp();
    t0 = fb2[lane]; t1 = fb2[lane + 32];
#pragma unroll 8
    for (int f = 0; f < 64; f++) {
        float v = sx[f];
        t0 += v * fw2[lane * 64 + f];
        t1 += v * fw2[(lane + 32) * 64 + f];
    }
    h0 += (t0 > 0.0f ? t0 : 0.01f * t0);
    h1 += (t1 > 0.0f ? t1 : 0.01f * t1);

    m = warp_sum(h0 + h1) * (1.0f / 64.0f);
    d0 = h0 - m; d1 = h1 - m;
    var = warp_sum(d0 * d0 + d1 * d1) * (1.0f / 64.0f);
    r = rsqrtf(var + 1e-5f);
    float z0 = d0 * r * ln2g[lane] + ln2b[lane];
    float z1 = d1 * r * ln2g[lane + 32] + ln2b[lane + 32];

    float l0 = warp_sum(z0 * fw3[lane] + z1 * fw3[lane + 32]);
    float l1 = warp_sum(z0 * fw3[64 + lane] + z1 * fw3[64 + lane + 32]);
    if (lane == 0) {
        l0 += fb3[0]; l1 += fb3[1];
        *outp = 1.0f / (1.0f + expf(l0 - l1));
    }
    __syncwarp();
}

// ---------------- fused step kernel ----------------------------------------
// grid (16, BS), block 512 = 16 warps, each warp 2 nodes.
// Weight layout: e-row-major, stride 68 -> LDS.128 of own row conflict-free;
// A-matvec split: warp w computes e-half (w>>3) of A row (w&7).
// smem (floats):
//   sW1a 4352 | sW1b 4352 | sW2 4352 | sM1 16*512 | sA 512 | sHH 16*64 |
//   sHX 16*64 | sB2 64 | sEW 8 | sSH 8   = 23888 fl = 95552 B -> 2 blocks/SM
#define SW_STRIDE 68
#define SMEM_FLOATS 23888
#define SMEM_BYTES  (SMEM_FLOATS * 4)

__global__ __launch_bounds__(512, 2) void k_step(
    const float* __restrict__ hcur, float* __restrict__ hnext, int t,
    const int* __restrict__ skill,
    const float* __restrict__ fc1w, const float* __restrict__ fc1b,
    const float* __restrict__ fc2w, const float* __restrict__ fc2b,
    const float* __restrict__ fw1, const float* __restrict__ fb1,
    const float* __restrict__ ln1g, const float* __restrict__ ln1b,
    const float* __restrict__ fw2, const float* __restrict__ fb2,
    const float* __restrict__ ln2g, const float* __restrict__ ln2b,
    const float* __restrict__ fw3, const float* __restrict__ fb3,
    float* __restrict__ out) {

    extern __shared__ float s[];
    float* sW1a = s;                   // [e][f] stride 68
    float* sW1b = s + 4352;
    float* sW2  = s + 8704;
    float* sM1  = s + 13056;           // per-warp [8 l][64 f]
    float* sA   = s + 21248;           // [8 l][64 e]
    float* sHH  = s + 21760;           // per-warp hh row (A phase)
    float* sHX  = s + 22784;           // per-warp hidden row / fnet scratch
    float* sB2  = s + 23808;
    float* sEW  = s + 23872;
    int*   sSH  = (int*)(s + 23880);

    int b = blockIdx.y;
    int g = blockIdx.x;
    int tid = threadIdx.x;
    int w = tid >> 5;
    int lane = tid & 31;

    // --- stage weights (coalesced gmem read, stride-68 rows) ---
    for (int idx = tid; idx < 64 * 128; idx += 512) {
        int e = idx >> 7, c = idx & 127;
        float v = fc1w[idx];
        if (c < 64) sW1a[e * SW_STRIDE + c] = v;
        else        sW1b[e * SW_STRIDE + (c - 64)] = v;
    }
    for (int idx = tid; idx < 64 * 64; idx += 512) {
        int e = idx >> 6, f = idx & 63;
        sW2[e * SW_STRIDE + f] = fc2w[idx];
    }
    if (tid < 64) sB2[tid] = fc2b[tid];
    if (tid < 8) {
        sEW[tid] = g_ew[(t * BS + b) * LL + tid];
        sSH[tid] = skill[b * TT + t + tid];
    }
    __syncthreads();

    float* mysx = sHX + w * 64;
    const unsigned long long* hvx = (const unsigned long long*)mysx;
    const ulonglong2* w1bA = (const ulonglong2*)(sW1b + lane * SW_STRIDE);
    const ulonglong2* w1bB = (const ulonglong2*)(sW1b + (lane + 32) * SW_STRIDE);
    const ulonglong2* w2A  = (const ulonglong2*)(sW2 + lane * SW_STRIDE);
    const ulonglong2* w2B  = (const ulonglong2*)(sW2 + (lane + 32) * SW_STRIDE);

    int n0 = (((g << 4) + w) << 1);      // warp's two nodes

    // --- phase 1 (all 16 warps busy):
    //     (a) half-row of A: warp w does e-half (w>>3) of row (w&7)
    //     (b) node-0 hidden load + B-matvec (independent of A)
    float B0c, B1c;   // B for node 0, carried into the node loop
    {
        int r = w & 7;
        int eh = (w >> 3) << 5;          // 0 or 32
        int e = eh + lane;
        int sl = sSH[r];
        // own copy of hh row for broadcast (no cross-warp dependency)
        sHH[w * 64 + lane]      = hcur[((b << 9) + sl) * EE + lane];
        sHH[w * 64 + lane + 32] = hcur[((b << 9) + sl) * EE + lane + 32];
        // node-0 hidden row
        mysx[lane]      = hcur[((b << 9) + n0) * EE + lane];
        mysx[lane + 32] = hcur[((b << 9) + n0) * EE + lane + 32];
        __syncwarp();

        // A half-row: one output per lane
        const ulonglong2* wa = (const ulonglong2*)(sW1a + e * SW_STRIDE);
        const unsigned long long* hh = (const unsigned long long*)(sHH + w * 64);
        unsigned long long aa = 0ull;
#pragma unroll
        for (int fp = 0; fp < 16; fp++) {
            ulonglong2 q = wa[fp];
            fma2(aa, hh[2 * fp], q.x);
            fma2(aa, hh[2 * fp + 1], q.y);
        }
        sA[r * 64 + e] = red2(aa) + __ldg(&fc1b[e]);

        // node-0 B-matvec (2 outputs per lane)
        unsigned long long bp0 = 0ull, bp1 = 0ull;
#pragma unroll
        for (int fp = 0; fp < 16; fp++) {
            ulonglong2 qa = w1bA[fp];
            ulonglong2 qb = w1bB[fp];
            unsigned long long m01 = hvx[2 * fp], m23 = hvx[2 * fp + 1];
            fma2(bp0, m01, qa.x); fma2(bp0, m23, qa.y);
            fma2(bp1, m01, qb.x); fma2(bp1, m23, qb.y);
        }
        B0c = red2(bp0);
        B1c = red2(bp1);
    }
    __syncthreads();

    int tgt = __ldg(&skill[b * TT + t + LL]);
    float* myM1 = sM1 + w * 512;
    const ulonglong2* mv2 = (const ulonglong2*)myM1;

#pragma unroll 1
    for (int i = 0; i < 2; i++) {
        int n = n0 + i;
        float B0, B1;
        if (i == 0) {
            B0 = B0c; B1 = B1c;
        } else {
            // node-1 hidden + B-matvec
            mysx[lane]      = hcur[((b << 9) + n) * EE + lane];
            mysx[lane + 32] = hcur[((b << 9) + n) * EE + lane + 32];
            __syncwarp();
            unsigned long long bp0 = 0ull, bp1 = 0ull;
#pragma unroll
            for (int fp = 0; fp < 16; fp++) {
                ulonglong2 qa = w1bA[fp];
                ulonglong2 qb = w1bB[fp];
                unsigned long long m01 = hvx[2 * fp], m23 = hvx[2 * fp + 1];
                fma2(bp0, m01, qa.x); fma2(bp0, m23, qa.y);
                fma2(bp1, m01, qb.x); fma2(bp1, m23, qb.y);
            }
            B0 = red2(bp0);
            B1 = red2(bp1);
        }

        // msg1 = tanh(A + B)   (single-MUFU tanh)
#pragma unroll
        for (int l = 0; l < 8; l++) {
            myM1[l * 64 + lane]      = tanha(sA[l * 64 + lane] + B0);
            myM1[l * 64 + lane + 32] = tanha(sA[l * 64 + lane + 32] + B1);
        }
        __syncwarp();

        // fc2 for all 8 l's at once (32 packed accumulators)
        unsigned long long acc0[8], acc1[8];
#pragma unroll
        for (int l = 0; l < 8; l++) { acc0[l] = 0ull; acc1[l] = 0ull; }
#pragma unroll 4
        for (int fp = 0; fp < 16; fp++) {
            ulonglong2 qa = w2A[fp];
            ulonglong2 qb = w2B[fp];
#pragma unroll
            for (int l = 0; l < 8; l++) {
                ulonglong2 m = mv2[l * 16 + fp];
                fma2(acc0[l], m.x, qa.x); fma2(acc0[l], m.y, qa.y);
                fma2(acc1[l], m.x, qb.x); fma2(acc1[l], m.y, qb.y);
            }
        }

        // S rows (uniform L2-resident loads)
        float wr0[8], wr1[8];
#pragma unroll
        for (int l = 0; l < 8; l++) {
            wr0[l] = __ldg(&g_S[(((size_t)b * 2 + 0) * NROWS + (t + l)) * NN + n]);
            wr1[l] = __ldg(&g_S[(((size_t)b * 2 + 1) * NROWS + (t + l)) * NN + n]);
        }

        // msg2 = tanh(.+b2)*ew ; agg over l with S weights
        float b20 = sB2[lane], b21 = sB2[lane + 32];
        float ag00 = 0, ag01 = 0, ag10 = 0, ag11 = 0;
#pragma unroll
        for (int l = 0; l < 8; l++) {
            float ewl = sEW[l];
            float m0 = tanha(red2(acc0[l]) + b20) * ewl;
            float m1 = tanha(red2(acc1[l]) + b21) * ewl;
            ag00 += wr0[l] * m0;  ag01 += wr0[l] * m1;
            ag10 += wr1[l] * m0;  ag11 += wr1[l] * m1;
        }

        // new_hidden = mean over k
        hnext[((b << 9) + n) * EE + lane]      = 0.5f * (ag00 + ag10);
        hnext[((b << 9) + n) * EE + lane + 32] = 0.5f * (ag01 + ag11);

        // prediction head only at the target node
        if (n == tgt) {
            fnet_warp(ag00, ag01, lane, mysx, fw1, fb1, ln1g, ln1b,
                      fw2, fb2, ln2g, ln2b, fw3, fb3,
                      &out[(t * BS + b) * 2 + 0]);
            fnet_warp(ag10, ag11, lane, mysx, fw1, fb1, ln1g, ln1b,
                      fw2, fb2, ln2g, ln2b, fw3, fb3,
                      &out[(t * BS + b) * 2 + 1]);
        }
        __syncwarp();
    }
}

// ---------------- launch ----------------------------------------------------
extern "C" void kernel_launch(void* const* d_in, const int* in_sizes, int n_in,
                              void* d_out, int out_size) {
    const int*   skill = (const int*)d_in[0];
    const int*   timeq = (const int*)d_in[1];
    const int*   label = (const int*)d_in[2];
    const float* adj   = (const float*)d_in[3];
    const float* emb   = (const float*)d_in[4];
    const float* fc1w  = (const float*)d_in[5];
    const float* fc1b  = (const float*)d_in[6];
    const float* fc2w  = (const float*)d_in[7];
    const float* fc2b  = (const float*)d_in[8];
    const float* fw1   = (const float*)d_in[9];
    const float* fb1   = (const float*)d_in[10];
    const float* ln1g  = (const float*)d_in[11];
    const float* ln1b  = (const float*)d_in[12];
    const float* fw2   = (const float*)d_in[13];
    const float* fb2   = (const float*)d_in[14];
    const float* ln2g  = (const float*)d_in[15];
    const float* ln2b  = (const float*)d_in[16];
    const float* fw3   = (const float*)d_in[17];
    const float* fb3   = (const float*)d_in[18];
    float* out = (float*)d_out;

    cudaFuncSetAttribute(k_step, cudaFuncAttributeMaxDynamicSharedMemorySize, SMEM_BYTES);

    float *hA, *hB;
    cudaGetSymbolAddress((void**)&hA, g_hA);
    cudaGetSymbolAddress((void**)&hB, g_hB);

    k_init_hidden<<<dim3(BS, NN / 4), 256>>>(skill, label, emb, hA);
    k_ew<<<3, 512>>>(timeq);
    k_S<<<dim3(4, 2, BS), 128>>>(skill, adj);

    for (int t = 0; t < STEPS; t++) {
        const float* hc = (t & 1) ? hB : hA;
        float*       hn = (t & 1) ? hA : hB;
        k_step<<<dim3(16, BS), 512, SMEM_BYTES>>>(
            hc, hn, t, skill,
            fc1w, fc1b, fc2w, fc2b,
            fw1, fb1, ln1g, ln1b, fw2, fb2, ln2g, ln2b, fw3, fb3,
            out);
    }
}